// round 11
// baseline (speedup 1.0000x reference)
#include <cuda_runtime.h>
#include <math.h>

#define Bsz 128
#define Tsz 256
#define Lw  4
#define DCc 128
#define DWw 128
#define Hh  256
#define Vv  6000
#define NEGV -1e30f
#define CLSZ 16

// ---------------- device global scratch (no allocations allowed) ----------------
__device__ float g_proj[Vv * Lw * DCc];                 // PROJ[ch][w][e]
__device__ float g_word[(size_t)Tsz * Bsz * Lw * DWw];  // word[t][b][w][e]
__device__ float g_su[Tsz * Bsz * Lw];                  // su[t][b][w]
__device__ float g_rh[8 * Bsz * Hh];                    // h ring [slot][b][u]
__device__ float g_rc[8 * Bsz * Hh];                    // c ring
__device__ float g_rp[8 * Bsz * DWw];                   // pred ring [slot][b][e]
__device__ int   g_best_i[Bsz];

__device__ __forceinline__ float sigm(float x) { return 1.0f / (1.0f + expf(-x)); }

// ---------------- hardware cluster barrier (release-acquire, cluster scope) --------
__device__ __forceinline__ void cbar() {
    asm volatile("barrier.cluster.arrive.aligned;" ::: "memory");
    asm volatile("barrier.cluster.wait.aligned;" ::: "memory");
}

// ---------------- PROJ table (148 blocks = 1 wave, 2 chars/iter, 4 accumulators) ----
__global__ void k_proj(const float* __restrict__ emb,
                       const float* __restrict__ rW,
                       const float* __restrict__ rb,
                       const float* __restrict__ cW,
                       const float* __restrict__ cb) {
    extern __shared__ float sm[];
    float* srW = sm;               // 16384
    float* scW = srW + 16384;      // 16384
    float* srb = scW + 16384;      // 128
    float* scb = srb + 128;        // 128
    float* se  = scb + 128;        // 256
    float* sh  = se + 256;         // 256
    const int tid = threadIdx.x;   // 256 threads
    const int e = tid & 127, half = tid >> 7;
    const int w = blockIdx.y;

    for (int i = tid; i < 16384; i += 256) {
        srW[i] = rW[w * 16384 + i];
        scW[i] = cW[i];
    }
    if (tid < 128) { srb[tid] = rb[w * 128 + tid]; scb[tid] = cb[tid]; }
    __syncthreads();

    const int base = blockIdx.x * 163;
    for (int ci = 0; ci < 82; ci++) {
        const int ch = base + ci * 2 + half;
        const bool ok = (ci * 2 + half < 163) && (ch < Vv);
        se[half * 128 + e] = ok ? emb[ch * 128 + e] : 0.0f;
        __syncthreads();
        const float* seh = se + half * 128;
        float a0 = srb[e], a1 = 0.f, a2 = 0.f, a3 = 0.f;
        #pragma unroll 8
        for (int d = 0; d < 128; d += 4) {
            a0 = fmaf(seh[d + 0], srW[(d + 0) * 128 + e], a0);
            a1 = fmaf(seh[d + 1], srW[(d + 1) * 128 + e], a1);
            a2 = fmaf(seh[d + 2], srW[(d + 2) * 128 + e], a2);
            a3 = fmaf(seh[d + 3], srW[(d + 3) * 128 + e], a3);
        }
        float g = (a0 + a1) + (a2 + a3);
        sh[half * 128 + e] = sigm(g) * seh[e];
        __syncthreads();
        const float* shh = sh + half * 128;
        float p0 = scb[e], p1 = 0.f, p2 = 0.f, p3 = 0.f;
        #pragma unroll 8
        for (int d = 0; d < 128; d += 4) {
            p0 = fmaf(shh[d + 0], scW[(d + 0) * 128 + e], p0);
            p1 = fmaf(shh[d + 1], scW[(d + 1) * 128 + e], p1);
            p2 = fmaf(shh[d + 2], scW[(d + 2) * 128 + e], p2);
            p3 = fmaf(shh[d + 3], scW[(d + 3) * 128 + e], p3);
        }
        float p = (p0 + p1) + (p2 + p3);
        if (ok) g_proj[(ch * Lw + w) * DCc + e] = tanhf(p);
        __syncthreads();
    }
}

// ---------------- word + su tables ----------------
__global__ void k_word(const int* __restrict__ chars, const float* __restrict__ U) {
    const int t = blockIdx.x, b = blockIdx.y, tid = threadIdx.x; // 128 threads
    const int lane = tid & 31, wid = tid >> 5;
    __shared__ int ch[4];
    __shared__ float red[4];
    if (tid < 4) {
        int ti = t - tid;
        ch[tid] = (ti >= 0) ? chars[b * Tsz + ti] : 0;
    }
    __syncthreads();
    const float inv[4] = {1.0f, 0.5f, 1.0f / 3.0f, 0.25f};
    const float uw = U[tid];
    #pragma unroll
    for (int w = 0; w < 4; w++) {
        float acc = 0.0f;
        for (int c = 0; c <= w; c++) acc += g_proj[(ch[c] * Lw + w) * DCc + tid];
        acc *= inv[w];
        g_word[(((size_t)t * Bsz + b) * Lw + w) * DWw + tid] = acc;
        float v = acc * uw;
        #pragma unroll
        for (int o = 16; o; o >>= 1) v += __shfl_xor_sync(0xffffffffu, v, o);
        if (lane == 0) red[wid] = v;
        __syncthreads();
        if (tid == 0) g_su[(t * Bsz + b) * Lw + w] = red[0] + red[1] + red[2] + red[3];
        __syncthreads();
    }
}

// ---------------- init: c1,h1,pred0; prefill rings slots 4..7 ----------------------
__global__ void k_init(const float* __restrict__ lk, const float* __restrict__ lb,
                       const float* __restrict__ pW, const float* __restrict__ pb,
                       const float* __restrict__ bos) {
    __shared__ float sh1[256], sc1[256], sp0[128];
    const int u = threadIdx.x;  // 256 threads
    const int b = blockIdx.x;
    float zi = lb[u], zj = lb[256 + u], zo = lb[768 + u];
    for (int d = 0; d < 128; d++) {
        float x = bos[d];
        const float* row = lk + d * 1024;
        zi = fmaf(x, row[u], zi);
        zj = fmaf(x, row[256 + u], zj);
        zo = fmaf(x, row[768 + u], zo);
    }
    float nc = sigm(zi) * tanhf(zj);      // c0 = 0
    float nh = tanhf(nc) * sigm(zo);
    sc1[u] = nc; sh1[u] = nh;
    __syncthreads();
    if (u < 128) {
        float p = pb[u];
        for (int q = 0; q < 256; q++) p = fmaf(sh1[q], pW[q * 128 + u], p);
        sp0[u] = tanhf(p);
    }
    __syncthreads();
    for (int s = 4; s < 8; s++) {
        g_rc[(s * Bsz + b) * Hh + u] = sc1[u];
        g_rh[(s * Bsz + b) * Hh + u] = sh1[u];
        if (u < 128) g_rp[(s * Bsz + b) * DWw + u] = sp0[u];
    }
}

// ---------------- persistent sequential kernel ----------------
// CTA b: P1 (pred/score/argmax) for row b; P2 (LSTM) for rows bg*16..+15 x units
// ug*16..+15 (bg=b>>4, ug=b&15). Groups are 16-CTA clusters; the two per-step
// sync points are hardware cluster barriers (release-acquire, cluster scope).
__global__ void __launch_bounds__(256, 1) __cluster_dims__(CLSZ, 1, 1) k_run(
    const float* __restrict__ lk, const float* __restrict__ lb,
    const float* __restrict__ pW, const float* __restrict__ pb,
    float* __restrict__ out) {
    extern __shared__ float sm[];
    float* spw   = sm;              // 32768: pred_W [u][e]
    float* swl   = spw + 32768;     // 24576: Wl[k][uu*4+g]
    float* sxh   = swl + 24576;     // 256
    float* spred = sxh + 256;       // 128
    float* sred  = spred + 128;     // 256
    float* sbias = sred + 256;      // 64
    float* ssc   = sbias + 64;      // 8

    const int tid = threadIdx.x;
    const int b = blockIdx.x;
    const int bg = b >> 4, ug = b & 15;
    const int lane = tid & 31, wid = tid >> 5;
    const int r = tid >> 4, uu = tid & 15;       // P2 roles
    const int bb = bg * 16 + r;
    const int unit = ug * 16 + uu;
    const int e1 = tid & 127, hf = tid >> 7;

    for (int i = tid; i < 32768; i += 256) spw[i] = pW[i];
    for (int i = tid; i < 24576; i += 256) {
        int k = i >> 6, m = i & 63, u2 = m >> 2, g = m & 3;
        swl[i] = lk[k * 1024 + g * 256 + ug * 16 + u2];
    }
    if (tid < 64) { int u2 = tid >> 2, g = tid & 3; sbias[tid] = lb[g * 256 + ug * 16 + u2]; }
    const float rpb = (tid < 128) ? pb[tid] : 0.0f;
    __syncthreads();

    float* out_sc = out;
    float* out_wl = out + Bsz * Tsz;

    for (int t = 0; t < Tsz; t++) {
        // ================= P1: pred + score + argmax (row b) =================
        const int slot1 = (t + 7) & 7;  // (t-1) mod 8
        sxh[tid] = __ldcg(&g_rh[(slot1 * Bsz + b) * Hh + tid]);
        __syncthreads();
        {   // 256-length GEMV split across both halves, 4 accumulators
            const float* qs = sxh + hf * 128;
            const float* wb = spw + hf * 16384 + e1;
            float a0 = 0.f, a1 = 0.f, a2 = 0.f, a3 = 0.f;
            #pragma unroll 8
            for (int q = 0; q < 128; q += 4) {
                a0 = fmaf(qs[q + 0], wb[(q + 0) * 128], a0);
                a1 = fmaf(qs[q + 1], wb[(q + 1) * 128], a1);
                a2 = fmaf(qs[q + 2], wb[(q + 2) * 128], a2);
                a3 = fmaf(qs[q + 3], wb[(q + 3) * 128], a3);
            }
            sred[tid] = (a0 + a1) + (a2 + a3);
        }
        __syncthreads();
        if (tid < 128) {
            float p = tanhf(rpb + sred[tid] + sred[128 + tid]);
            spred[tid] = p;
            g_rp[(slot1 * Bsz + b) * DWw + tid] = p;   // own-CTA ring
        }
        __syncthreads();
        if (wid < 4) {
            float s = NEGV;
            if (wid <= t) {
                const float* wp = &g_word[(((size_t)t * Bsz + b) * Lw + wid) * DWw];
                float acc = 0.0f;
                if (wid == 0) {
                    for (int e = lane; e < 128; e += 32) acc = fmaf(spred[e], wp[e], acc);
                } else {
                    const float* pp = &g_rp[(((t - 1 - wid) & 7) * Bsz + b) * DWw];
                    for (int e = lane; e < 128; e += 32) acc = fmaf(pp[e], wp[e], acc);
                }
                #pragma unroll
                for (int o = 16; o; o >>= 1) acc += __shfl_xor_sync(0xffffffffu, acc, o);
                if (lane == 0) s = acc + g_su[(t * Bsz + b) * Lw + wid];
            }
            if (lane == 0) ssc[wid] = s;
        }
        __syncthreads();
        if (tid == 0) {
            int best = 0; float bs = ssc[0];
            #pragma unroll
            for (int w = 1; w < 4; w++) if (ssc[w] > bs) { bs = ssc[w]; best = w; }
            __stcg(&g_best_i[b], best);
            out_sc[b * Tsz + t] = bs;
            out_wl[b * Tsz + t] = (float)(best + 1);
        }
        cbar();   // P1 results visible cluster-wide

        // ================= P2: LSTM for 16 rows x 16 units =================
        {
            const int best = __ldcg(&g_best_i[bb]);
            const int hs = (t - 1 - best) & 7;
            float zi = sbias[uu * 4 + 0], zj = sbias[uu * 4 + 1];
            float zf = sbias[uu * 4 + 2], zo = sbias[uu * 4 + 3];
            const float4* xw = (const float4*)&g_word[(((size_t)t * Bsz + bb) * Lw + best) * DWw];
            #pragma unroll 4
            for (int kq = 0; kq < 32; kq++) {
                float4 x4 = __ldcg(xw + kq);
                const float* w0 = &swl[(kq * 4) * 64 + uu * 4];
                float4 a = *(const float4*)(w0);
                float4 c = *(const float4*)(w0 + 64);
                float4 d = *(const float4*)(w0 + 128);
                float4 e = *(const float4*)(w0 + 192);
                zi = fmaf(x4.x, a.x, zi); zj = fmaf(x4.x, a.y, zj); zf = fmaf(x4.x, a.z, zf); zo = fmaf(x4.x, a.w, zo);
                zi = fmaf(x4.y, c.x, zi); zj = fmaf(x4.y, c.y, zj); zf = fmaf(x4.y, c.z, zf); zo = fmaf(x4.y, c.w, zo);
                zi = fmaf(x4.z, d.x, zi); zj = fmaf(x4.z, d.y, zj); zf = fmaf(x4.z, d.z, zf); zo = fmaf(x4.z, d.w, zo);
                zi = fmaf(x4.w, e.x, zi); zj = fmaf(x4.w, e.y, zj); zf = fmaf(x4.w, e.z, zf); zo = fmaf(x4.w, e.w, zo);
            }
            const float4* hw = (const float4*)&g_rh[(hs * Bsz + bb) * Hh];
            #pragma unroll 4
            for (int kq = 0; kq < 64; kq++) {
                float4 x4 = __ldcg(hw + kq);
                const float* w0 = &swl[(128 + kq * 4) * 64 + uu * 4];
                float4 a = *(const float4*)(w0);
                float4 c = *(const float4*)(w0 + 64);
                float4 d = *(const float4*)(w0 + 128);
                float4 e = *(const float4*)(w0 + 192);
                zi = fmaf(x4.x, a.x, zi); zj = fmaf(x4.x, a.y, zj); zf = fmaf(x4.x, a.z, zf); zo = fmaf(x4.x, a.w, zo);
                zi = fmaf(x4.y, c.x, zi); zj = fmaf(x4.y, c.y, zj); zf = fmaf(x4.y, c.z, zf); zo = fmaf(x4.y, c.w, zo);
                zi = fmaf(x4.z, d.x, zi); zj = fmaf(x4.z, d.y, zj); zf = fmaf(x4.z, d.z, zf); zo = fmaf(x4.z, d.w, zo);
                zi = fmaf(x4.w, e.x, zi); zj = fmaf(x4.w, e.y, zj); zf = fmaf(x4.w, e.z, zf); zo = fmaf(x4.w, e.w, zo);
            }
            float cp = __ldcg(&g_rc[(hs * Bsz + bb) * Hh + unit]);
            float nc = cp * sigm(zf) + sigm(zi) * tanhf(zj);
            float nh = tanhf(nc) * sigm(zo);
            const int ws = t & 7;
            __stcg(&g_rc[(ws * Bsz + bb) * Hh + unit], nc);
            __stcg(&g_rh[(ws * Bsz + bb) * Hh + unit], nh);
        }
        cbar();   // P2 ring writes visible cluster-wide
    }
}

// ---------------- launch ----------------
static const int PROJ_SMEM = (16384 + 16384 + 128 + 128 + 256 + 256) * 4;
static const int RUN_SMEM  = (32768 + 24576 + 256 + 128 + 256 + 64 + 8) * 4;

extern "C" void kernel_launch(void* const* d_in, const int* in_sizes, int n_in,
                              void* d_out, int out_size) {
    const int*   chars = (const int*)d_in[0];
    const float* emb   = (const float*)d_in[1];
    const float* rW    = (const float*)d_in[2];
    const float* rb    = (const float*)d_in[3];
    const float* cW    = (const float*)d_in[4];
    const float* cb    = (const float*)d_in[5];
    const float* lk    = (const float*)d_in[6];
    const float* lb    = (const float*)d_in[7];
    const float* pW    = (const float*)d_in[8];
    const float* pb    = (const float*)d_in[9];
    const float* U     = (const float*)d_in[10];
    const float* bos   = (const float*)d_in[11];

    cudaFuncSetAttribute(k_proj, cudaFuncAttributeMaxDynamicSharedMemorySize, PROJ_SMEM);
    cudaFuncSetAttribute(k_run,  cudaFuncAttributeMaxDynamicSharedMemorySize, RUN_SMEM);
    cudaFuncSetAttribute(k_run,  cudaFuncAttributeNonPortableClusterSizeAllowed, 1);

    k_init<<<Bsz, 256>>>(lk, lb, pW, pb, bos);
    k_proj<<<dim3(37, 4), 256, PROJ_SMEM>>>(emb, rW, rb, cW, cb);
    k_word<<<dim3(Tsz, Bsz), 128>>>(chars, U);
    k_run<<<Bsz, 256, RUN_SMEM>>>(lk, lb, pW, pb, (float*)d_out);
}

// round 12
// speedup vs baseline: 1.4441x; 1.4441x over previous
#include <cuda_runtime.h>
#include <math.h>

#define Bsz 128
#define Tsz 256
#define Lw  4
#define DCc 128
#define DWw 128
#define Hh  256
#define Vv  6000
#define NEGV -1e30f

typedef unsigned long long u64t;

// ---------------- device global scratch (no allocations allowed) ----------------
__device__ float g_proj[Vv * Lw * DCc];                       // PROJ[ch][w][e]
__device__ __align__(16) float g_wordd[(size_t)Tsz * Bsz * Lw * 256]; // word duplicated pairs
__device__ float g_su[Tsz * Bsz * Lw];                        // su[t][b][w]
__device__ __align__(16) float g_rhd[8 * Bsz * 512];          // h ring duplicated pairs
__device__ float g_rc[8 * Bsz * Hh];                          // c ring (plain)
__device__ float g_rp[8 * Bsz * DWw];                         // pred ring (plain)
__device__ int   g_best_i[Bsz];
__device__ unsigned g_arr[8 * 32];                            // per-group barrier counters

__device__ __forceinline__ float sigm(float x) { return 1.0f / (1.0f + expf(-x)); }

// ---------------- packed f32x2 helpers ----------------
__device__ __forceinline__ u64t fma2(u64t a, u64t b, u64t c) {
    u64t d; asm("fma.rn.f32x2 %0, %1, %2, %3;" : "=l"(d) : "l"(a), "l"(b), "l"(c)); return d;
}
__device__ __forceinline__ u64t pk2(float lo, float hi) {
    u64t r; asm("mov.b64 %0, {%1, %2};" : "=l"(r) : "f"(lo), "f"(hi)); return r;
}
__device__ __forceinline__ float2 unpk(u64t v) {
    float2 r; asm("mov.b64 {%0, %1}, %2;" : "=f"(r.x), "=f"(r.y) : "l"(v)); return r;
}

// ---------------- 16-CTA group barrier (monotonic epoch; reset by k_init) ----------
__device__ __forceinline__ void gbar(unsigned* ctr, unsigned target) {
    __syncthreads();
    if (threadIdx.x == 0) {
        __threadfence();
        atomicAdd(ctr, 1u);
        volatile unsigned* p = ctr;
        while (*p < target) { }
        __threadfence();
    }
    __syncthreads();
}

// ---------------- PROJ table (148 blocks = 1 wave, 2 chars/iter, 4 accumulators) ----
__global__ void k_proj(const float* __restrict__ emb,
                       const float* __restrict__ rW,
                       const float* __restrict__ rb,
                       const float* __restrict__ cW,
                       const float* __restrict__ cb) {
    extern __shared__ float sm[];
    float* srW = sm;               // 16384
    float* scW = srW + 16384;      // 16384
    float* srb = scW + 16384;      // 128
    float* scb = srb + 128;        // 128
    float* se  = scb + 128;        // 256
    float* sh  = se + 256;         // 256
    const int tid = threadIdx.x;   // 256 threads
    const int e = tid & 127, half = tid >> 7;
    const int w = blockIdx.y;

    for (int i = tid; i < 16384; i += 256) {
        srW[i] = rW[w * 16384 + i];
        scW[i] = cW[i];
    }
    if (tid < 128) { srb[tid] = rb[w * 128 + tid]; scb[tid] = cb[tid]; }
    __syncthreads();

    const int base = blockIdx.x * 163;
    for (int ci = 0; ci < 82; ci++) {
        const int ch = base + ci * 2 + half;
        const bool ok = (ci * 2 + half < 163) && (ch < Vv);
        se[half * 128 + e] = ok ? emb[ch * 128 + e] : 0.0f;
        __syncthreads();
        const float* seh = se + half * 128;
        float a0 = srb[e], a1 = 0.f, a2 = 0.f, a3 = 0.f;
        #pragma unroll 8
        for (int d = 0; d < 128; d += 4) {
            a0 = fmaf(seh[d + 0], srW[(d + 0) * 128 + e], a0);
            a1 = fmaf(seh[d + 1], srW[(d + 1) * 128 + e], a1);
            a2 = fmaf(seh[d + 2], srW[(d + 2) * 128 + e], a2);
            a3 = fmaf(seh[d + 3], srW[(d + 3) * 128 + e], a3);
        }
        float g = (a0 + a1) + (a2 + a3);
        sh[half * 128 + e] = sigm(g) * seh[e];
        __syncthreads();
        const float* shh = sh + half * 128;
        float p0 = scb[e], p1 = 0.f, p2 = 0.f, p3 = 0.f;
        #pragma unroll 8
        for (int d = 0; d < 128; d += 4) {
            p0 = fmaf(shh[d + 0], scW[(d + 0) * 128 + e], p0);
            p1 = fmaf(shh[d + 1], scW[(d + 1) * 128 + e], p1);
            p2 = fmaf(shh[d + 2], scW[(d + 2) * 128 + e], p2);
            p3 = fmaf(shh[d + 3], scW[(d + 3) * 128 + e], p3);
        }
        float p = (p0 + p1) + (p2 + p3);
        if (ok) g_proj[(ch * Lw + w) * DCc + e] = tanhf(p);
        __syncthreads();
    }
}

// ---------------- word (duplicated pairs) + su tables ----------------
__global__ void k_word(const int* __restrict__ chars, const float* __restrict__ U) {
    const int t = blockIdx.x, b = blockIdx.y, tid = threadIdx.x; // 128 threads
    const int lane = tid & 31, wid = tid >> 5;
    __shared__ int ch[4];
    __shared__ float red[4];
    if (tid < 4) {
        int ti = t - tid;
        ch[tid] = (ti >= 0) ? chars[b * Tsz + ti] : 0;
    }
    __syncthreads();
    const float inv[4] = {1.0f, 0.5f, 1.0f / 3.0f, 0.25f};
    const float uw = U[tid];
    #pragma unroll
    for (int w = 0; w < 4; w++) {
        float acc = 0.0f;
        for (int c = 0; c <= w; c++) acc += g_proj[(ch[c] * Lw + w) * DCc + tid];
        acc *= inv[w];
        *(float2*)&g_wordd[(((size_t)t * Bsz + b) * Lw + w) * 256 + tid * 2] = make_float2(acc, acc);
        float v = acc * uw;
        #pragma unroll
        for (int o = 16; o; o >>= 1) v += __shfl_xor_sync(0xffffffffu, v, o);
        if (lane == 0) red[wid] = v;
        __syncthreads();
        if (tid == 0) g_su[(t * Bsz + b) * Lw + w] = red[0] + red[1] + red[2] + red[3];
        __syncthreads();
    }
}

// ---------------- init: c1,h1,pred0; prefill rings slots 4..7; reset barriers -------
__global__ void k_init(const float* __restrict__ lk, const float* __restrict__ lb,
                       const float* __restrict__ pW, const float* __restrict__ pb,
                       const float* __restrict__ bos) {
    __shared__ float sh1[256], sc1[256], sp0[128];
    const int u = threadIdx.x;  // 256 threads
    const int b = blockIdx.x;
    float zi = lb[u], zj = lb[256 + u], zo = lb[768 + u];
    for (int d = 0; d < 128; d++) {
        float x = bos[d];
        const float* row = lk + d * 1024;
        zi = fmaf(x, row[u], zi);
        zj = fmaf(x, row[256 + u], zj);
        zo = fmaf(x, row[768 + u], zo);
    }
    float nc = sigm(zi) * tanhf(zj);      // c0 = 0
    float nh = tanhf(nc) * sigm(zo);
    sc1[u] = nc; sh1[u] = nh;
    __syncthreads();
    if (u < 128) {
        float p = pb[u];
        for (int q = 0; q < 256; q++) p = fmaf(sh1[q], pW[q * 128 + u], p);
        sp0[u] = tanhf(p);
    }
    __syncthreads();
    for (int s = 4; s < 8; s++) {
        g_rc[(s * Bsz + b) * Hh + u] = sc1[u];
        *(float2*)&g_rhd[((size_t)(s * Bsz + b)) * 512 + u * 2] = make_float2(sh1[u], sh1[u]);
        if (u < 128) g_rp[(s * Bsz + b) * DWw + u] = sp0[u];
    }
    if (b == 0 && u < 8) g_arr[u * 32] = 0u;
}

// ---------------- persistent sequential kernel ----------------
// CTA b: P1 (pred/score/argmax) for row b; P2 (LSTM) for rows bg*16..+15 x units
// ug*16..+15 (bg=b>>4, ug=b&15). P2 warp layout: 4 rows x 8 units (halves the
// weight-LDS crossbar). Gates packed (i,j)/(f,o) as f32x2 single chains in
// ascending K -> bit-identical to the scalar R9 version.
__global__ void __launch_bounds__(256, 1) k_run(
    const float* __restrict__ lk, const float* __restrict__ lb,
    const float* __restrict__ pW, const float* __restrict__ pb,
    float* __restrict__ out) {
    extern __shared__ float sm[];
    float* spw   = sm;              // 32768: pred_W [u][e]
    float* swl   = spw + 32768;     // 24576: Wl[k][uu*4+g]
    float* sxh   = swl + 24576;     // 256
    float* spred = sxh + 256;       // 128
    float* sred  = spred + 128;     // 256
    float* sbias = sred + 256;      // 64
    float* ssc   = sbias + 64;      // 8

    const int tid = threadIdx.x;
    const int b = blockIdx.x;
    const int bg = b >> 4, ug = b & 15;
    const int lane = tid & 31, warp = tid >> 5;
    const int rt = warp >> 1;                      // row tile 0..3
    const int lrow = rt * 4 + (lane >> 3);         // 0..15
    const int lunit = (warp & 1) * 8 + (lane & 7); // 0..15
    const int bb = bg * 16 + lrow;
    const int unit = ug * 16 + lunit;
    const int e1 = tid & 127, hf = tid >> 7;

    for (int i = tid; i < 32768; i += 256) spw[i] = pW[i];
    for (int i = tid; i < 24576; i += 256) {
        int k = i >> 6, m = i & 63, u2 = m >> 2, g = m & 3;
        swl[i] = lk[k * 1024 + g * 256 + ug * 16 + u2];
    }
    if (tid < 64) { int u2 = tid >> 2, g = tid & 3; sbias[tid] = lb[g * 256 + ug * 16 + u2]; }
    const float rpb = (tid < 128) ? pb[tid] : 0.0f;
    __syncthreads();

    unsigned nbar = 0;
    float* out_sc = out;
    float* out_wl = out + Bsz * Tsz;
    unsigned* bar = &g_arr[bg * 32];

    for (int t = 0; t < Tsz; t++) {
        // ================= P1: pred + score + argmax (row b) =================
        const int slot1 = (t + 7) & 7;  // (t-1) mod 8
        sxh[tid] = __ldcg(&g_rhd[((size_t)(slot1 * Bsz + b)) * 512 + tid * 2]);
        __syncthreads();
        {   // 256-length GEMV split across both halves, 4 accumulators
            const float* qs = sxh + hf * 128;
            const float* wb = spw + hf * 16384 + e1;
            float a0 = 0.f, a1 = 0.f, a2 = 0.f, a3 = 0.f;
            #pragma unroll 8
            for (int q = 0; q < 128; q += 4) {
                a0 = fmaf(qs[q + 0], wb[(q + 0) * 128], a0);
                a1 = fmaf(qs[q + 1], wb[(q + 1) * 128], a1);
                a2 = fmaf(qs[q + 2], wb[(q + 2) * 128], a2);
                a3 = fmaf(qs[q + 3], wb[(q + 3) * 128], a3);
            }
            sred[tid] = (a0 + a1) + (a2 + a3);
        }
        __syncthreads();
        if (tid < 128) {
            float p = tanhf(rpb + sred[tid] + sred[128 + tid]);
            spred[tid] = p;
            g_rp[(slot1 * Bsz + b) * DWw + tid] = p;   // own-CTA ring
        }
        __syncthreads();
        if (warp < 4) {
            float s = NEGV;
            if (warp <= t) {
                const float* wp = &g_wordd[(((size_t)t * Bsz + b) * Lw + warp) * 256];
                float acc = 0.0f;
                if (warp == 0) {
                    for (int e = lane; e < 128; e += 32) acc = fmaf(spred[e], __ldcg(wp + e * 2), acc);
                } else {
                    const float* pp = &g_rp[(((t - 1 - warp) & 7) * Bsz + b) * DWw];
                    for (int e = lane; e < 128; e += 32) acc = fmaf(__ldcg(pp + e), __ldcg(wp + e * 2), acc);
                }
                #pragma unroll
                for (int o = 16; o; o >>= 1) acc += __shfl_xor_sync(0xffffffffu, acc, o);
                if (lane == 0) s = acc + g_su[(t * Bsz + b) * Lw + warp];
            }
            if (lane == 0) ssc[warp] = s;
        }
        __syncthreads();
        if (tid == 0) {
            int best = 0; float bs = ssc[0];
            #pragma unroll
            for (int w = 1; w < 4; w++) if (ssc[w] > bs) { bs = ssc[w]; best = w; }
            __stcg(&g_best_i[b], best);
            out_sc[b * Tsz + t] = bs;
            out_wl[b * Tsz + t] = (float)(best + 1);
        }
        nbar++; gbar(bar, nbar * 16u);

        // ================= P2: LSTM for 16 rows x 16 units =================
        {
            const int best = __ldcg(&g_best_i[bb]);
            const int hs = (t - 1 - best) & 7;
            u64t aij = pk2(sbias[lunit * 4 + 0], sbias[lunit * 4 + 1]);
            u64t afo = pk2(sbias[lunit * 4 + 2], sbias[lunit * 4 + 3]);

            // x part: K = 0..127 (duplicated pairs, 2 K per 16B load)
            const ulonglong2* xd = (const ulonglong2*)&g_wordd[(((size_t)t * Bsz + bb) * Lw + best) * 256];
            #pragma unroll 8
            for (int k2 = 0; k2 < 64; k2++) {
                ulonglong2 xx = __ldcg(xd + k2);
                const ulonglong2* wr = (const ulonglong2*)&swl[(k2 * 2) * 64 + lunit * 4];
                ulonglong2 wa = wr[0];    // K = 2*k2
                ulonglong2 wb2 = wr[16];  // K = 2*k2+1
                aij = fma2(xx.x, wa.x, aij);  afo = fma2(xx.x, wa.y, afo);
                aij = fma2(xx.y, wb2.x, aij); afo = fma2(xx.y, wb2.y, afo);
            }
            // h part: K = 128..383
            const ulonglong2* hd = (const ulonglong2*)&g_rhd[((size_t)(hs * Bsz + bb)) * 512];
            #pragma unroll 8
            for (int k2 = 0; k2 < 128; k2++) {
                ulonglong2 xx = __ldcg(hd + k2);
                const ulonglong2* wr = (const ulonglong2*)&swl[(128 + k2 * 2) * 64 + lunit * 4];
                ulonglong2 wa = wr[0];
                ulonglong2 wb2 = wr[16];
                aij = fma2(xx.x, wa.x, aij);  afo = fma2(xx.x, wa.y, afo);
                aij = fma2(xx.y, wb2.x, aij); afo = fma2(xx.y, wb2.y, afo);
            }
            float2 fij = unpk(aij), ffo = unpk(afo);
            float cp = __ldcg(&g_rc[(hs * Bsz + bb) * Hh + unit]);
            float nc = cp * sigm(ffo.x) + sigm(fij.x) * tanhf(fij.y);
            float nh = tanhf(nc) * sigm(ffo.y);
            const int ws = t & 7;
            __stcg(&g_rc[(ws * Bsz + bb) * Hh + unit], nc);
            __stcg((float2*)&g_rhd[((size_t)(ws * Bsz + bb)) * 512 + unit * 2], make_float2(nh, nh));
        }
        nbar++; gbar(bar, nbar * 16u);
    }
}

// ---------------- launch ----------------
static const int PROJ_SMEM = (16384 + 16384 + 128 + 128 + 256 + 256) * 4;
static const int RUN_SMEM  = (32768 + 24576 + 256 + 128 + 256 + 64 + 8) * 4;

extern "C" void kernel_launch(void* const* d_in, const int* in_sizes, int n_in,
                              void* d_out, int out_size) {
    const int*   chars = (const int*)d_in[0];
    const float* emb   = (const float*)d_in[1];
    const float* rW    = (const float*)d_in[2];
    const float* rb    = (const float*)d_in[3];
    const float* cW    = (const float*)d_in[4];
    const float* cb    = (const float*)d_in[5];
    const float* lk    = (const float*)d_in[6];
    const float* lb    = (const float*)d_in[7];
    const float* pW    = (const float*)d_in[8];
    const float* pb    = (const float*)d_in[9];
    const float* U     = (const float*)d_in[10];
    const float* bos   = (const float*)d_in[11];

    cudaFuncSetAttribute(k_proj, cudaFuncAttributeMaxDynamicSharedMemorySize, PROJ_SMEM);
    cudaFuncSetAttribute(k_run,  cudaFuncAttributeMaxDynamicSharedMemorySize, RUN_SMEM);

    k_init<<<Bsz, 256>>>(lk, lb, pW, pb, bos);
    k_proj<<<dim3(37, 4), 256, PROJ_SMEM>>>(emb, rW, rb, cW, cb);
    k_word<<<dim3(Tsz, Bsz), 128>>>(chars, U);
    k_run<<<Bsz, 256, RUN_SMEM>>>(lk, lb, pW, pb, (float*)d_out);
}

// round 14
// speedup vs baseline: 1.7137x; 1.1867x over previous
#include <cuda_runtime.h>
#include <math.h>

#define Bsz 128
#define Tsz 256
#define Lw  4
#define DCc 128
#define DWw 128
#define Hh  256
#define Vv  6000
#define NEGV -1e30f

// ---------------- device global scratch (no allocations allowed) ----------------
__device__ float g_proj[Vv * Lw * DCc];                 // PROJ[ch][w][e]
__device__ float g_word[(size_t)Tsz * Bsz * Lw * DWw];  // word[t][b][w][e]
__device__ float g_su[Tsz * Bsz * Lw];                  // su[t][b][w]
__device__ float g_rh[8 * Bsz * Hh];                    // h ring [slot][b][u]
__device__ float g_rc[8 * Bsz * Hh];                    // c ring
__device__ float g_rp[8 * Bsz * DWw];                   // pred ring [slot][b][e]
__device__ int   g_best_i[Bsz];
__device__ unsigned g_arr[8 * 32];                      // per-group barrier counters (padded)

__device__ __forceinline__ float sigm(float x) { return 1.0f / (1.0f + expf(-x)); }

// ---------------- 16-CTA group barrier (monotonic epoch; reset by k_init) ----------
__device__ __forceinline__ void gbar(unsigned* ctr, unsigned target) {
    __syncthreads();
    if (threadIdx.x == 0) {
        __threadfence();
        atomicAdd(ctr, 1u);
        volatile unsigned* p = ctr;
        while (*p < target) { }
        __threadfence();
    }
    __syncthreads();
}

// ---------------- PROJ table (148 blocks = 1 wave, 2 chars/iter, 4 accumulators) ----
__global__ void k_proj(const float* __restrict__ emb,
                       const float* __restrict__ rW,
                       const float* __restrict__ rb,
                       const float* __restrict__ cW,
                       const float* __restrict__ cb) {
    extern __shared__ float sm[];
    float* srW = sm;               // 16384
    float* scW = srW + 16384;      // 16384
    float* srb = scW + 16384;      // 128
    float* scb = srb + 128;        // 128
    float* se  = scb + 128;        // 256
    float* sh  = se + 256;         // 256
    const int tid = threadIdx.x;   // 256 threads
    const int e = tid & 127, half = tid >> 7;
    const int w = blockIdx.y;

    for (int i = tid; i < 16384; i += 256) {
        srW[i] = rW[w * 16384 + i];
        scW[i] = cW[i];
    }
    if (tid < 128) { srb[tid] = rb[w * 128 + tid]; scb[tid] = cb[tid]; }
    __syncthreads();

    const int base = blockIdx.x * 163;
    for (int ci = 0; ci < 82; ci++) {
        const int ch = base + ci * 2 + half;
        const bool ok = (ci * 2 + half < 163) && (ch < Vv);
        se[half * 128 + e] = ok ? emb[ch * 128 + e] : 0.0f;
        __syncthreads();
        const float* seh = se + half * 128;
        float a0 = srb[e], a1 = 0.f, a2 = 0.f, a3 = 0.f;
        #pragma unroll 8
        for (int d = 0; d < 128; d += 4) {
            a0 = fmaf(seh[d + 0], srW[(d + 0) * 128 + e], a0);
            a1 = fmaf(seh[d + 1], srW[(d + 1) * 128 + e], a1);
            a2 = fmaf(seh[d + 2], srW[(d + 2) * 128 + e], a2);
            a3 = fmaf(seh[d + 3], srW[(d + 3) * 128 + e], a3);
        }
        float g = (a0 + a1) + (a2 + a3);
        sh[half * 128 + e] = sigm(g) * seh[e];
        __syncthreads();
        const float* shh = sh + half * 128;
        float p0 = scb[e], p1 = 0.f, p2 = 0.f, p3 = 0.f;
        #pragma unroll 8
        for (int d = 0; d < 128; d += 4) {
            p0 = fmaf(shh[d + 0], scW[(d + 0) * 128 + e], p0);
            p1 = fmaf(shh[d + 1], scW[(d + 1) * 128 + e], p1);
            p2 = fmaf(shh[d + 2], scW[(d + 2) * 128 + e], p2);
            p3 = fmaf(shh[d + 3], scW[(d + 3) * 128 + e], p3);
        }
        float p = (p0 + p1) + (p2 + p3);
        if (ok) g_proj[(ch * Lw + w) * DCc + e] = tanhf(p);
        __syncthreads();
    }
}

// ---------------- word + su tables ----------------
__global__ void k_word(const int* __restrict__ chars, const float* __restrict__ U) {
    const int t = blockIdx.x, b = blockIdx.y, tid = threadIdx.x; // 128 threads
    const int lane = tid & 31, wid = tid >> 5;
    __shared__ int ch[4];
    __shared__ float red[4];
    if (tid < 4) {
        int ti = t - tid;
        ch[tid] = (ti >= 0) ? chars[b * Tsz + ti] : 0;
    }
    __syncthreads();
    const float inv[4] = {1.0f, 0.5f, 1.0f / 3.0f, 0.25f};
    const float uw = U[tid];
    #pragma unroll
    for (int w = 0; w < 4; w++) {
        float acc = 0.0f;
        for (int c = 0; c <= w; c++) acc += g_proj[(ch[c] * Lw + w) * DCc + tid];
        acc *= inv[w];
        g_word[(((size_t)t * Bsz + b) * Lw + w) * DWw + tid] = acc;
        float v = acc * uw;
        #pragma unroll
        for (int o = 16; o; o >>= 1) v += __shfl_xor_sync(0xffffffffu, v, o);
        if (lane == 0) red[wid] = v;
        __syncthreads();
        if (tid == 0) g_su[(t * Bsz + b) * Lw + w] = red[0] + red[1] + red[2] + red[3];
        __syncthreads();
    }
}

// ---------------- init: c1,h1,pred0; prefill rings slots 4..7; reset barriers -------
__global__ void k_init(const float* __restrict__ lk, const float* __restrict__ lb,
                       const float* __restrict__ pW, const float* __restrict__ pb,
                       const float* __restrict__ bos) {
    __shared__ float sh1[256], sc1[256], sp0[128];
    const int u = threadIdx.x;  // 256 threads
    const int b = blockIdx.x;
    float zi = lb[u], zj = lb[256 + u], zo = lb[768 + u];
    for (int d = 0; d < 128; d++) {
        float x = bos[d];
        const float* row = lk + d * 1024;
        zi = fmaf(x, row[u], zi);
        zj = fmaf(x, row[256 + u], zj);
        zo = fmaf(x, row[768 + u], zo);
    }
    float nc = sigm(zi) * tanhf(zj);      // c0 = 0
    float nh = tanhf(nc) * sigm(zo);
    sc1[u] = nc; sh1[u] = nh;
    __syncthreads();
    if (u < 128) {
        float p = pb[u];
        for (int q = 0; q < 256; q++) p = fmaf(sh1[q], pW[q * 128 + u], p);
        sp0[u] = tanhf(p);
    }
    __syncthreads();
    for (int s = 4; s < 8; s++) {
        g_rc[(s * Bsz + b) * Hh + u] = sc1[u];
        g_rh[(s * Bsz + b) * Hh + u] = sh1[u];
        if (u < 128) g_rp[(s * Bsz + b) * DWw + u] = sp0[u];
    }
    if (b == 0 && u < 8) g_arr[u * 32] = 0u;
}

// ---------------- persistent sequential kernel ----------------
// CTA b: P1 (pred/score/argmax) for row b; P2 (LSTM) for rows bg*16..+15 x units
// ug*16..+15 (bg=b>>4, ug=b&15). P2 warp layout: 4 rows x 8 units — weight LDS
// is 128B-distinct per warp (1 crossbar phase) with 8-lane broadcast per row.
// Sync: two 16-CTA group barriers per step (all cross-CTA deps are intra-group).
__global__ void __launch_bounds__(256, 1) k_run(
    const float* __restrict__ lk, const float* __restrict__ lb,
    const float* __restrict__ pW, const float* __restrict__ pb,
    float* __restrict__ out) {
    extern __shared__ float sm[];
    float* spw   = sm;              // 32768: pred_W [u][e]
    float* swl   = spw + 32768;     // 24576: Wl[k][uu*4+g]
    float* sxh   = swl + 24576;     // 256
    float* spred = sxh + 256;       // 128
    float* sred  = spred + 128;     // 256
    float* sbias = sred + 256;      // 64
    float* ssc   = sbias + 64;      // 8

    const int tid = threadIdx.x;
    const int b = blockIdx.x;
    const int bg = b >> 4, ug = b & 15;
    const int lane = tid & 31, warp = tid >> 5;
    const int rt = warp >> 1;                      // row tile 0..3
    const int lrow = rt * 4 + (lane >> 3);         // 0..15
    const int lunit = (warp & 1) * 8 + (lane & 7); // 0..15
    const int bb = bg * 16 + lrow;
    const int unit = ug * 16 + lunit;
    const int e1 = tid & 127, hf = tid >> 7;

    for (int i = tid; i < 32768; i += 256) spw[i] = pW[i];
    for (int i = tid; i < 24576; i += 256) {
        int k = i >> 6, m = i & 63, u2 = m >> 2, g = m & 3;
        swl[i] = lk[k * 1024 + g * 256 + ug * 16 + u2];
    }
    if (tid < 64) { int u2 = tid >> 2, g = tid & 3; sbias[tid] = lb[g * 256 + ug * 16 + u2]; }
    const float rpb = (tid < 128) ? pb[tid] : 0.0f;
    __syncthreads();

    unsigned nbar = 0;
    float* out_sc = out;
    float* out_wl = out + Bsz * Tsz;
    unsigned* bar = &g_arr[bg * 32];

    for (int t = 0; t < Tsz; t++) {
        // ================= P1: pred + score + argmax (row b) =================
        const int slot1 = (t + 7) & 7;  // (t-1) mod 8
        sxh[tid] = __ldcg(&g_rh[(slot1 * Bsz + b) * Hh + tid]);
        __syncthreads();
        {   // 256-length GEMV split across both halves, 4 accumulators
            const float* qs = sxh + hf * 128;
            const float* wb = spw + hf * 16384 + e1;
            float a0 = 0.f, a1 = 0.f, a2 = 0.f, a3 = 0.f;
            #pragma unroll 8
            for (int q = 0; q < 128; q += 4) {
                a0 = fmaf(qs[q + 0], wb[(q + 0) * 128], a0);
                a1 = fmaf(qs[q + 1], wb[(q + 1) * 128], a1);
                a2 = fmaf(qs[q + 2], wb[(q + 2) * 128], a2);
                a3 = fmaf(qs[q + 3], wb[(q + 3) * 128], a3);
            }
            sred[tid] = (a0 + a1) + (a2 + a3);
        }
        __syncthreads();
        if (tid < 128) {
            float p = tanhf(rpb + sred[tid] + sred[128 + tid]);
            spred[tid] = p;
            g_rp[(slot1 * Bsz + b) * DWw + tid] = p;   // own-CTA ring
        }
        __syncthreads();
        if (warp < 4) {
            float s = NEGV;
            if (warp <= t) {
                const float* wp = &g_word[(((size_t)t * Bsz + b) * Lw + warp) * DWw];
                float acc = 0.0f;
                if (warp == 0) {
                    for (int e = lane; e < 128; e += 32) acc = fmaf(spred[e], wp[e], acc);
                } else {
                    const float* pp = &g_rp[(((t - 1 - warp) & 7) * Bsz + b) * DWw];
                    for (int e = lane; e < 128; e += 32) acc = fmaf(pp[e], wp[e], acc);
                }
                #pragma unroll
                for (int o = 16; o; o >>= 1) acc += __shfl_xor_sync(0xffffffffu, acc, o);
                if (lane == 0) s = acc + g_su[(t * Bsz + b) * Lw + warp];
            }
            if (lane == 0) ssc[warp] = s;
        }
        __syncthreads();
        if (tid == 0) {
            int best = 0; float bs = ssc[0];
            #pragma unroll
            for (int w = 1; w < 4; w++) if (ssc[w] > bs) { bs = ssc[w]; best = w; }
            __stcg(&g_best_i[b], best);
            out_sc[b * Tsz + t] = bs;
            out_wl[b * Tsz + t] = (float)(best + 1);
        }
        nbar++; gbar(bar, nbar * 16u);

        // ================= P2: LSTM for 16 rows x 16 units (4x8 per warp) =========
        {
            const int best = __ldcg(&g_best_i[bb]);
            const int hs = (t - 1 - best) & 7;
            float zi = sbias[lunit * 4 + 0], zj = sbias[lunit * 4 + 1];
            float zf = sbias[lunit * 4 + 2], zo = sbias[lunit * 4 + 3];
            const float4* xw = (const float4*)&g_word[(((size_t)t * Bsz + bb) * Lw + best) * DWw];
            #pragma unroll 4
            for (int kq = 0; kq < 32; kq++) {
                float4 x4 = __ldcg(xw + kq);
                const float* w0 = &swl[(kq * 4) * 64 + lunit * 4];
                float4 a = *(const float4*)(w0);
                float4 c = *(const float4*)(w0 + 64);
                float4 d = *(const float4*)(w0 + 128);
                float4 e = *(const float4*)(w0 + 192);
                zi = fmaf(x4.x, a.x, zi); zj = fmaf(x4.x, a.y, zj); zf = fmaf(x4.x, a.z, zf); zo = fmaf(x4.x, a.w, zo);
                zi = fmaf(x4.y, c.x, zi); zj = fmaf(x4.y, c.y, zj); zf = fmaf(x4.y, c.z, zf); zo = fmaf(x4.y, c.w, zo);
                zi = fmaf(x4.z, d.x, zi); zj = fmaf(x4.z, d.y, zj); zf = fmaf(x4.z, d.z, zf); zo = fmaf(x4.z, d.w, zo);
                zi = fmaf(x4.w, e.x, zi); zj = fmaf(x4.w, e.y, zj); zf = fmaf(x4.w, e.z, zf); zo = fmaf(x4.w, e.w, zo);
            }
            const float4* hw = (const float4*)&g_rh[(hs * Bsz + bb) * Hh];
            #pragma unroll 4
            for (int kq = 0; kq < 64; kq++) {
                float4 x4 = __ldcg(hw + kq);
                const float* w0 = &swl[(128 + kq * 4) * 64 + lunit * 4];
                float4 a = *(const float4*)(w0);
                float4 c = *(const float4*)(w0 + 64);
                float4 d = *(const float4*)(w0 + 128);
                float4 e = *(const float4*)(w0 + 192);
                zi = fmaf(x4.x, a.x, zi); zj = fmaf(x4.x, a.y, zj); zf = fmaf(x4.x, a.z, zf); zo = fmaf(x4.x, a.w, zo);
                zi = fmaf(x4.y, c.x, zi); zj = fmaf(x4.y, c.y, zj); zf = fmaf(x4.y, c.z, zf); zo = fmaf(x4.y, c.w, zo);
                zi = fmaf(x4.z, d.x, zi); zj = fmaf(x4.z, d.y, zj); zf = fmaf(x4.z, d.z, zf); zo = fmaf(x4.z, d.w, zo);
                zi = fmaf(x4.w, e.x, zi); zj = fmaf(x4.w, e.y, zj); zf = fmaf(x4.w, e.z, zf); zo = fmaf(x4.w, e.w, zo);
            }
            float cp = __ldcg(&g_rc[(hs * Bsz + bb) * Hh + unit]);
            float nc = cp * sigm(zf) + sigm(zi) * tanhf(zj);
            float nh = tanhf(nc) * sigm(zo);
            const int ws = t & 7;
            __stcg(&g_rc[(ws * Bsz + bb) * Hh + unit], nc);
            __stcg(&g_rh[(ws * Bsz + bb) * Hh + unit], nh);
        }
        nbar++; gbar(bar, nbar * 16u);
    }
}

// ---------------- launch ----------------
static const int PROJ_SMEM = (16384 + 16384 + 128 + 128 + 256 + 256) * 4;
static const int RUN_SMEM  = (32768 + 24576 + 256 + 128 + 256 + 64 + 8) * 4;

extern "C" void kernel_launch(void* const* d_in, const int* in_sizes, int n_in,
                              void* d_out, int out_size) {
    const int*   chars = (const int*)d_in[0];
    const float* emb   = (const float*)d_in[1];
    const float* rW    = (const float*)d_in[2];
    const float* rb    = (const float*)d_in[3];
    const float* cW    = (const float*)d_in[4];
    const float* cb    = (const float*)d_in[5];
    const float* lk    = (const float*)d_in[6];
    const float* lb    = (const float*)d_in[7];
    const float* pW    = (const float*)d_in[8];
    const float* pb    = (const float*)d_in[9];
    const float* U     = (const float*)d_in[10];
    const float* bos   = (const float*)d_in[11];

    cudaFuncSetAttribute(k_proj, cudaFuncAttributeMaxDynamicSharedMemorySize, PROJ_SMEM);
    cudaFuncSetAttribute(k_run,  cudaFuncAttributeMaxDynamicSharedMemorySize, RUN_SMEM);

    k_init<<<Bsz, 256>>>(lk, lb, pW, pb, bos);
    k_proj<<<dim3(37, 4), 256, PROJ_SMEM>>>(emb, rW, rb, cW, cb);
    k_word<<<dim3(Tsz, Bsz), 128>>>(chars, U);
    k_run<<<Bsz, 256, RUN_SMEM>>>(lk, lb, pW, pb, (float*)d_out);
}

// round 15
// speedup vs baseline: 1.8167x; 1.0601x over previous
#include <cuda_runtime.h>
#include <math.h>

#define Bsz 128
#define Tsz 256
#define Lw  4
#define DCc 128
#define DWw 128
#define Hh  256
#define Vv  6000
#define NEGV -1e30f
#define PPSZ (Bsz * 16 * 128)

// ---------------- device global scratch (no allocations allowed) ----------------
__device__ float g_proj[Vv * Lw * DCc];                 // PROJ[ch][w][e]
__device__ float g_word[(size_t)Tsz * Bsz * Lw * DWw];  // word[t][b][w][e]
__device__ float g_su[Tsz * Bsz * Lw];                  // su[t][b][w]
__device__ float g_rh[8 * Bsz * Hh];                    // h ring [slot][b][u]
__device__ float g_rc[8 * Bsz * Hh];                    // c ring
__device__ float g_rp[8 * Bsz * DWw];                   // pred ring [slot][b][e]
__device__ __align__(16) float g_pp[2 * PPSZ];          // pred partials [buf][b][ug][e]
__device__ int   g_best_i[Bsz];
__device__ unsigned g_arr[8 * 32];                      // per-group barrier counters (padded)

__device__ __forceinline__ float sigm(float x) { return 1.0f / (1.0f + expf(-x)); }

// ---------------- 16-CTA group barrier (monotonic epoch; reset by k_init) ----------
__device__ __forceinline__ void gbar(unsigned* ctr, unsigned target) {
    __syncthreads();
    if (threadIdx.x == 0) {
        __threadfence();
        atomicAdd(ctr, 1u);
        volatile unsigned* p = ctr;
        while (*p < target) { }
        __threadfence();
    }
    __syncthreads();
}

// ---------------- PROJ table (148 blocks = 1 wave, 2 chars/iter, 4 accumulators) ----
__global__ void k_proj(const float* __restrict__ emb,
                       const float* __restrict__ rW,
                       const float* __restrict__ rb,
                       const float* __restrict__ cW,
                       const float* __restrict__ cb) {
    extern __shared__ float sm[];
    float* srW = sm;               // 16384
    float* scW = srW + 16384;      // 16384
    float* srb = scW + 16384;      // 128
    float* scb = srb + 128;        // 128
    float* se  = scb + 128;        // 256
    float* sh  = se + 256;         // 256
    const int tid = threadIdx.x;   // 256 threads
    const int e = tid & 127, half = tid >> 7;
    const int w = blockIdx.y;

    for (int i = tid; i < 16384; i += 256) {
        srW[i] = rW[w * 16384 + i];
        scW[i] = cW[i];
    }
    if (tid < 128) { srb[tid] = rb[w * 128 + tid]; scb[tid] = cb[tid]; }
    __syncthreads();

    const int base = blockIdx.x * 163;
    for (int ci = 0; ci < 82; ci++) {
        const int ch = base + ci * 2 + half;
        const bool ok = (ci * 2 + half < 163) && (ch < Vv);
        se[half * 128 + e] = ok ? emb[ch * 128 + e] : 0.0f;
        __syncthreads();
        const float* seh = se + half * 128;
        float a0 = srb[e], a1 = 0.f, a2 = 0.f, a3 = 0.f;
        #pragma unroll 8
        for (int d = 0; d < 128; d += 4) {
            a0 = fmaf(seh[d + 0], srW[(d + 0) * 128 + e], a0);
            a1 = fmaf(seh[d + 1], srW[(d + 1) * 128 + e], a1);
            a2 = fmaf(seh[d + 2], srW[(d + 2) * 128 + e], a2);
            a3 = fmaf(seh[d + 3], srW[(d + 3) * 128 + e], a3);
        }
        float g = (a0 + a1) + (a2 + a3);
        sh[half * 128 + e] = sigm(g) * seh[e];
        __syncthreads();
        const float* shh = sh + half * 128;
        float p0 = scb[e], p1 = 0.f, p2 = 0.f, p3 = 0.f;
        #pragma unroll 8
        for (int d = 0; d < 128; d += 4) {
            p0 = fmaf(shh[d + 0], scW[(d + 0) * 128 + e], p0);
            p1 = fmaf(shh[d + 1], scW[(d + 1) * 128 + e], p1);
            p2 = fmaf(shh[d + 2], scW[(d + 2) * 128 + e], p2);
            p3 = fmaf(shh[d + 3], scW[(d + 3) * 128 + e], p3);
        }
        float p = (p0 + p1) + (p2 + p3);
        if (ok) g_proj[(ch * Lw + w) * DCc + e] = tanhf(p);
        __syncthreads();
    }
}

// ---------------- word + su tables ----------------
__global__ void k_word(const int* __restrict__ chars, const float* __restrict__ U) {
    const int t = blockIdx.x, b = blockIdx.y, tid = threadIdx.x; // 128 threads
    const int lane = tid & 31, wid = tid >> 5;
    __shared__ int ch[4];
    __shared__ float red[4];
    if (tid < 4) {
        int ti = t - tid;
        ch[tid] = (ti >= 0) ? chars[b * Tsz + ti] : 0;
    }
    __syncthreads();
    const float inv[4] = {1.0f, 0.5f, 1.0f / 3.0f, 0.25f};
    const float uw = U[tid];
    #pragma unroll
    for (int w = 0; w < 4; w++) {
        float acc = 0.0f;
        for (int c = 0; c <= w; c++) acc += g_proj[(ch[c] * Lw + w) * DCc + tid];
        acc *= inv[w];
        g_word[(((size_t)t * Bsz + b) * Lw + w) * DWw + tid] = acc;
        float v = acc * uw;
        #pragma unroll
        for (int o = 16; o; o >>= 1) v += __shfl_xor_sync(0xffffffffu, v, o);
        if (lane == 0) red[wid] = v;
        __syncthreads();
        if (tid == 0) g_su[(t * Bsz + b) * Lw + w] = red[0] + red[1] + red[2] + red[3];
        __syncthreads();
    }
}

// ---------------- init: c1,h1,pred0; rings slots 4..7; pp buf0; barriers ------------
__global__ void k_init(const float* __restrict__ lk, const float* __restrict__ lb,
                       const float* __restrict__ pW, const float* __restrict__ pb,
                       const float* __restrict__ bos) {
    __shared__ float sh1[256], sc1[256], sp0[128];
    const int u = threadIdx.x;  // 256 threads
    const int b = blockIdx.x;
    float zi = lb[u], zj = lb[256 + u], zo = lb[768 + u];
    for (int d = 0; d < 128; d++) {
        float x = bos[d];
        const float* row = lk + d * 1024;
        zi = fmaf(x, row[u], zi);
        zj = fmaf(x, row[256 + u], zj);
        zo = fmaf(x, row[768 + u], zo);
    }
    float nc = sigm(zi) * tanhf(zj);      // c0 = 0
    float nh = tanhf(nc) * sigm(zo);
    sc1[u] = nc; sh1[u] = nh;
    __syncthreads();
    if (u < 128) {
        float p = pb[u];
        for (int q = 0; q < 256; q++) p = fmaf(sh1[q], pW[q * 128 + u], p);
        sp0[u] = tanhf(p);
    }
    __syncthreads();
    for (int s = 4; s < 8; s++) {
        g_rc[(s * Bsz + b) * Hh + u] = sc1[u];
        g_rh[(s * Bsz + b) * Hh + u] = sh1[u];
        if (u < 128) g_rp[(s * Bsz + b) * DWw + u] = sp0[u];
    }
    // pp buffer 0 for row b: partial[pg][e] = sum_{lu} h1[pg*16+lu] * pW[(pg*16+lu)*128+e]
    {
        const int pg = u >> 4, sub = u & 15;
        float a[8];
        #pragma unroll
        for (int j = 0; j < 8; j++) a[j] = 0.0f;
        for (int lu = 0; lu < 16; lu++) {
            float nv = sh1[pg * 16 + lu];
            const float* wr = &pW[(pg * 16 + lu) * 128 + sub * 8];
            #pragma unroll
            for (int j = 0; j < 8; j++) a[j] = fmaf(nv, wr[j], a[j]);
        }
        float* dst = &g_pp[((size_t)b * 16 + pg) * 128 + sub * 8];
        #pragma unroll
        for (int j = 0; j < 8; j++) dst[j] = a[j];
    }
    if (b == 0 && u < 8) g_arr[u * 32] = 0u;
}

// ---------------- persistent sequential kernel ----------------
// CTA b: P1 (pred assembly/score/argmax) for row b; P2 (LSTM + pred partial) for
// rows bg*16..+15 x units ug*16..+15 (bg=b>>4, ug=b&15). P2 warps: 4 rows x 8 units.
// Two 16-CTA group barriers per step order ALL cross-CTA traffic (incl. g_pp).
__global__ void __launch_bounds__(256, 1) k_run(
    const float* __restrict__ lk, const float* __restrict__ lb,
    const float* __restrict__ pW, const float* __restrict__ pb,
    float* __restrict__ out) {
    extern __shared__ float sm[];
    float* swl   = sm;               // 24576: Wl[k][uu*4+g]
    float* spws  = swl + 24576;      // 2048: pW slice [lu][e]
    float* snh   = spws + 2048;      // 256
    float* spred = snh + 256;        // 128
    float* sred  = spred + 128;      // 256
    float* sbias = sred + 256;       // 64
    float* ssc   = sbias + 64;       // 8

    const int tid = threadIdx.x;
    const int b = blockIdx.x;
    const int bg = b >> 4, ug = b & 15;
    const int lane = tid & 31, warp = tid >> 5;
    const int rt = warp >> 1;                      // row tile 0..3
    const int lrow = rt * 4 + (lane >> 3);         // 0..15
    const int lunit = (warp & 1) * 8 + (lane & 7); // 0..15
    const int bb = bg * 16 + lrow;
    const int unit = ug * 16 + lunit;
    const int e1 = tid & 127, hf = tid >> 7;

    for (int i = tid; i < 24576; i += 256) {
        int k = i >> 6, m = i & 63, u2 = m >> 2, g = m & 3;
        swl[i] = lk[k * 1024 + g * 256 + ug * 16 + u2];
    }
    for (int i = tid; i < 2048; i += 256) {
        int lu = i >> 7, ee = i & 127;
        spws[i] = pW[(ug * 16 + lu) * 128 + ee];
    }
    if (tid < 64) { int u2 = tid >> 2, g = tid & 3; sbias[tid] = lb[g * 256 + ug * 16 + u2]; }
    const float rpb = (tid < 128) ? pb[tid] : 0.0f;
    __syncthreads();

    unsigned nbar = 0;
    float* out_sc = out;
    float* out_wl = out + Bsz * Tsz;
    unsigned* bar = &g_arr[bg * 32];

    for (int t = 0; t < Tsz; t++) {
        // ================= P1: pred assembly + score + argmax (row b) ============
        // hoist score-phase global loads (DRAM) to overlap with pp-sum
        float wv0 = 0.f, wv1 = 0.f, wv2 = 0.f, wv3 = 0.f, suv = 0.f;
        const bool sc_act = (warp < 4) && (warp <= t);
        if (sc_act) {
            const float* wp = &g_word[(((size_t)t * Bsz + b) * Lw + warp) * DWw];
            wv0 = __ldcg(wp + lane);
            wv1 = __ldcg(wp + lane + 32);
            wv2 = __ldcg(wp + lane + 64);
            wv3 = __ldcg(wp + lane + 96);
            suv = __ldcg(&g_su[(t * Bsz + b) * Lw + warp]);
        }
        {   // sum 16 pred partials (8 per half-thread), stride-128 ldcg = MLP 8
            const float* ppb = &g_pp[(size_t)(t & 1) * PPSZ + ((size_t)b * 16 + hf * 8) * 128 + e1];
            float pa = 0.0f;
            #pragma unroll
            for (int j = 0; j < 8; j++) pa += __ldcg(ppb + j * 128);
            sred[tid] = pa;
        }
        __syncthreads();
        if (tid < 128) {
            float p = tanhf(rpb + sred[tid] + sred[128 + tid]);
            spred[tid] = p;
            g_rp[((t + 7) & 7) * Bsz * DWw + b * DWw + tid] = p;   // own-CTA ring
        }
        __syncthreads();
        if (warp < 4) {
            float s = NEGV;
            if (sc_act) {
                float acc;
                if (warp == 0) {
                    acc = spred[lane] * wv0;
                    acc = fmaf(spred[lane + 32], wv1, acc);
                    acc = fmaf(spred[lane + 64], wv2, acc);
                    acc = fmaf(spred[lane + 96], wv3, acc);
                } else {
                    const float* pp = &g_rp[(((t - 1 - warp) & 7) * Bsz + b) * DWw];
                    acc = __ldcg(pp + lane) * wv0;
                    acc = fmaf(__ldcg(pp + lane + 32), wv1, acc);
                    acc = fmaf(__ldcg(pp + lane + 64), wv2, acc);
                    acc = fmaf(__ldcg(pp + lane + 96), wv3, acc);
                }
                #pragma unroll
                for (int o = 16; o; o >>= 1) acc += __shfl_xor_sync(0xffffffffu, acc, o);
                if (lane == 0) s = acc + suv;
            }
            if (lane == 0) ssc[warp] = s;
        }
        __syncthreads();
        if (tid == 0) {
            int best = 0; float bs = ssc[0];
            #pragma unroll
            for (int w = 1; w < 4; w++) if (ssc[w] > bs) { bs = ssc[w]; best = w; }
            __stcg(&g_best_i[b], best);
            out_sc[b * Tsz + t] = bs;
            out_wl[b * Tsz + t] = (float)(best + 1);
        }
        nbar++; gbar(bar, nbar * 16u);

        // ================= P2: LSTM for 16 rows x 16 units (4x8 per warp) =========
        {
            const int best = __ldcg(&g_best_i[bb]);
            const int hs = (t - 1 - best) & 7;
            float zi = sbias[lunit * 4 + 0], zj = sbias[lunit * 4 + 1];
            float zf = sbias[lunit * 4 + 2], zo = sbias[lunit * 4 + 3];
            const float4* xw = (const float4*)&g_word[(((size_t)t * Bsz + bb) * Lw + best) * DWw];
            #pragma unroll 4
            for (int kq = 0; kq < 32; kq++) {
                float4 x4 = __ldcg(xw + kq);
                const float* w0 = &swl[(kq * 4) * 64 + lunit * 4];
                float4 a = *(const float4*)(w0);
                float4 c = *(const float4*)(w0 + 64);
                float4 d = *(const float4*)(w0 + 128);
                float4 e = *(const float4*)(w0 + 192);
                zi = fmaf(x4.x, a.x, zi); zj = fmaf(x4.x, a.y, zj); zf = fmaf(x4.x, a.z, zf); zo = fmaf(x4.x, a.w, zo);
                zi = fmaf(x4.y, c.x, zi); zj = fmaf(x4.y, c.y, zj); zf = fmaf(x4.y, c.z, zf); zo = fmaf(x4.y, c.w, zo);
                zi = fmaf(x4.z, d.x, zi); zj = fmaf(x4.z, d.y, zj); zf = fmaf(x4.z, d.z, zf); zo = fmaf(x4.z, d.w, zo);
                zi = fmaf(x4.w, e.x, zi); zj = fmaf(x4.w, e.y, zj); zf = fmaf(x4.w, e.z, zf); zo = fmaf(x4.w, e.w, zo);
            }
            const float4* hw = (const float4*)&g_rh[(hs * Bsz + bb) * Hh];
            #pragma unroll 4
            for (int kq = 0; kq < 64; kq++) {
                float4 x4 = __ldcg(hw + kq);
                const float* w0 = &swl[(128 + kq * 4) * 64 + lunit * 4];
                float4 a = *(const float4*)(w0);
                float4 c = *(const float4*)(w0 + 64);
                float4 d = *(const float4*)(w0 + 128);
                float4 e = *(const float4*)(w0 + 192);
                zi = fmaf(x4.x, a.x, zi); zj = fmaf(x4.x, a.y, zj); zf = fmaf(x4.x, a.z, zf); zo = fmaf(x4.x, a.w, zo);
                zi = fmaf(x4.y, c.x, zi); zj = fmaf(x4.y, c.y, zj); zf = fmaf(x4.y, c.z, zf); zo = fmaf(x4.y, c.w, zo);
                zi = fmaf(x4.z, d.x, zi); zj = fmaf(x4.z, d.y, zj); zf = fmaf(x4.z, d.z, zf); zo = fmaf(x4.z, d.w, zo);
                zi = fmaf(x4.w, e.x, zi); zj = fmaf(x4.w, e.y, zj); zf = fmaf(x4.w, e.z, zf); zo = fmaf(x4.w, e.w, zo);
            }
            float cp = __ldcg(&g_rc[(hs * Bsz + bb) * Hh + unit]);
            float nc = cp * sigm(zf) + sigm(zi) * tanhf(zj);
            float nh = tanhf(nc) * sigm(zo);
            const int ws = t & 7;
            __stcg(&g_rc[(ws * Bsz + bb) * Hh + unit], nc);
            __stcg(&g_rh[(ws * Bsz + bb) * Hh + unit], nh);
            snh[lrow * 16 + lunit] = nh;
        }
        __syncthreads();
        // pred partial from this CTA's 16 units (consumed by P1 at t+1 after barrier)
        {
            const int pr = tid >> 4, p8 = tid & 15;
            float4 acA = make_float4(0.f, 0.f, 0.f, 0.f);
            float4 acB = make_float4(0.f, 0.f, 0.f, 0.f);
            #pragma unroll
            for (int u = 0; u < 16; u++) {
                float nv = snh[pr * 16 + u];
                float4 wa = *(const float4*)&spws[u * 128 + p8 * 8];
                float4 wb = *(const float4*)&spws[u * 128 + p8 * 8 + 4];
                acA.x = fmaf(nv, wa.x, acA.x); acA.y = fmaf(nv, wa.y, acA.y);
                acA.z = fmaf(nv, wa.z, acA.z); acA.w = fmaf(nv, wa.w, acA.w);
                acB.x = fmaf(nv, wb.x, acB.x); acB.y = fmaf(nv, wb.y, acB.y);
                acB.z = fmaf(nv, wb.z, acB.z); acB.w = fmaf(nv, wb.w, acB.w);
            }
            float* dst = &g_pp[(size_t)((t + 1) & 1) * PPSZ +
                               ((size_t)(bg * 16 + pr) * 16 + ug) * 128 + p8 * 8];
            __stcg((float4*)dst, acA);
            __stcg((float4*)(dst + 4), acB);
        }
        nbar++; gbar(bar, nbar * 16u);
    }
}

// ---------------- launch ----------------
static const int PROJ_SMEM = (16384 + 16384 + 128 + 128 + 256 + 256) * 4;
static const int RUN_SMEM  = (24576 + 2048 + 256 + 128 + 256 + 64 + 8) * 4;

extern "C" void kernel_launch(void* const* d_in, const int* in_sizes, int n_in,
                              void* d_out, int out_size) {
    const int*   chars = (const int*)d_in[0];
    const float* emb   = (const float*)d_in[1];
    const float* rW    = (const float*)d_in[2];
    const float* rb    = (const float*)d_in[3];
    const float* cW    = (const float*)d_in[4];
    const float* cb    = (const float*)d_in[5];
    const float* lk    = (const float*)d_in[6];
    const float* lb    = (const float*)d_in[7];
    const float* pW    = (const float*)d_in[8];
    const float* pb    = (const float*)d_in[9];
    const float* U     = (const float*)d_in[10];
    const float* bos   = (const float*)d_in[11];

    cudaFuncSetAttribute(k_proj, cudaFuncAttributeMaxDynamicSharedMemorySize, PROJ_SMEM);
    cudaFuncSetAttribute(k_run,  cudaFuncAttributeMaxDynamicSharedMemorySize, RUN_SMEM);

    k_init<<<Bsz, 256>>>(lk, lb, pW, pb, bos);
    k_proj<<<dim3(37, 4), 256, PROJ_SMEM>>>(emb, rW, rb, cW, cb);
    k_word<<<dim3(Tsz, Bsz), 128>>>(chars, U);
    k_run<<<Bsz, 256, RUN_SMEM>>>(lk, lb, pW, pb, (float*)d_out);
}